// round 1
// baseline (speedup 1.0000x reference)
#include <cuda_runtime.h>

// Problem constants
#define BATCH 4
#define DD 128
#define HH 128
#define WW 128
#define SLICE (HH*WW)          // 16384
#define VOL   (DD*HH*WW)       // 2097152
#define VTOT  (BATCH*VOL)      // 8388608
#define WS 11
#define RAD 5

#define C1F 1.0e-4f            // 0.01^2
#define C2F 9.0e-4f            // 0.03^2

// Scratch: 5 convolved fields (mu1, mu2, E[x^2], E[y^2], E[xy]) after x+y conv.
// 5 * 8388608 * 4B = 167.8 MB, static device allocation (allowed).
__device__ float g_buf[5ull * VTOT];
__device__ float g_w[WS];
__device__ double g_acc;

// ---------------------------------------------------------------------------
// Prep: recover separable 1-D Gaussian from the 3-D window (row sums are exact
// since window = g (x) g (x) g and sum(g)=1). Also zero the accumulator so the
// kernel is graph-replay safe.
// ---------------------------------------------------------------------------
__global__ void prep_kernel(const float* __restrict__ window) {
    int i = threadIdx.x;
    if (i < WS) {
        float s = 0.f;
        #pragma unroll 11
        for (int j = 0; j < 121; ++j) s += window[i * 121 + j];
        g_w[i] = s;
    }
    if (i == 0) g_acc = 0.0;
}

// ---------------------------------------------------------------------------
// K1: fused x-conv + y-conv over 32x32 tiles of one (b,z) slice.
// Computes the 5 product fields on the fly from img1/img2 in shared memory.
// ---------------------------------------------------------------------------
#define TILE 32
#define IW   42   // TILE + 2*RAD
#define SIMS 45   // padded stride for image tiles  (conflict-free for stage1)
#define SINS 33   // padded stride for intermediates (conflict-free for stage2)

__global__ __launch_bounds__(256) void conv_xy_kernel(
    const float* __restrict__ img1, const float* __restrict__ img2)
{
    __shared__ float sIm1[IW][SIMS];
    __shared__ float sIm2[IW][SIMS];
    __shared__ float sInt[5][IW][SINS];
    __shared__ float sg[WS];

    const int tid = threadIdx.x;
    const int tx = blockIdx.x, ty = blockIdx.y, bz = blockIdx.z; // bz = b*128+z
    const int x0 = tx * TILE - RAD;
    const int y0 = ty * TILE - RAD;
    const size_t base = (size_t)bz * SLICE;

    if (tid < WS) sg[tid] = g_w[tid];

    // Load 42x42 input halo tiles (zero padding outside the volume in y/x).
    for (int i = tid; i < IW * IW; i += 256) {
        int yy = i / IW, xx = i - yy * IW;
        int gy = y0 + yy, gx = x0 + xx;
        float a = 0.f, b = 0.f;
        if ((unsigned)gy < HH && (unsigned)gx < WW) {
            size_t idx = base + (size_t)gy * WW + gx;
            a = __ldg(img1 + idx);
            b = __ldg(img2 + idx);
        }
        sIm1[yy][xx] = a;
        sIm2[yy][xx] = b;
    }
    __syncthreads();

    float g[WS];
    #pragma unroll
    for (int t = 0; t < WS; ++t) g[t] = sg[t];

    // Stage 1: x-conv of 5 fields. Each work item produces 4 consecutive x
    // outputs from a 14-wide register window (amortizes LDS).
    for (int item = tid; item < IW * 8; item += 256) {
        int yy = item >> 3;
        int xg = (item & 7) * 4;
        float a[14], b[14];
        #pragma unroll
        for (int t = 0; t < 14; ++t) {
            a[t] = sIm1[yy][xg + t];
            b[t] = sIm2[yy][xg + t];
        }
        #pragma unroll
        for (int o = 0; o < 4; ++o) {
            float s1 = 0.f, s2 = 0.f, s3 = 0.f, s4 = 0.f, s5 = 0.f;
            #pragma unroll
            for (int t = 0; t < WS; ++t) {
                float av = a[o + t], bv = b[o + t];
                float p = g[t] * av;
                float q = g[t] * bv;
                s1 += p;
                s2 += q;
                s3 += p * av;
                s4 += q * bv;
                s5 += p * bv;
            }
            sInt[0][yy][xg + o] = s1;
            sInt[1][yy][xg + o] = s2;
            sInt[2][yy][xg + o] = s3;
            sInt[3][yy][xg + o] = s4;
            sInt[4][yy][xg + o] = s5;
        }
    }
    __syncthreads();

    // Stage 2: y-conv -> global. Each item produces 8 consecutive y outputs of
    // one field at one x, from an 18-value register column.
    for (int i = tid; i < 640; i += 256) {
        int f = i >> 7;
        int rem = i & 127;
        int x = rem & 31;
        int yg = (rem >> 5) * 8;
        float r[18];
        #pragma unroll
        for (int t = 0; t < 18; ++t) r[t] = sInt[f][yg + t][x];
        float* outp = g_buf + (size_t)f * VTOT + base
                    + (size_t)(ty * TILE) * WW + (size_t)(tx * TILE) + x;
        #pragma unroll
        for (int o = 0; o < 8; ++o) {
            float s = 0.f;
            #pragma unroll
            for (int t = 0; t < WS; ++t) s += g[t] * r[o + t];
            outp[(size_t)(yg + o) * WW] = s;
        }
    }
}

// ---------------------------------------------------------------------------
// K2: z-conv (register ring buffers, 5 fields) + SSIM map + reduction.
// Block = 128 threads (x dim), handles one (b, y, z-chunk-of-32) column set.
// ---------------------------------------------------------------------------
__global__ __launch_bounds__(128) void conv_z_ssim_kernel()
{
    const int x  = threadIdx.x;
    const int zc = blockIdx.x;   // 0..3 (chunk of 32 z)
    const int y  = blockIdx.y;   // 0..127
    const int b  = blockIdx.z;   // 0..3
    const size_t colbase = (size_t)b * VOL + (size_t)y * WW + x;

    float w[WS];
    #pragma unroll
    for (int t = 0; t < WS; ++t) w[t] = g_w[t];

    float r0[WS], r1[WS], r2[WS], r3[WS], r4[WS];
    #pragma unroll
    for (int t = 0; t < WS; ++t) {
        int zz = zc * 32 - RAD + t;
        bool ok = (unsigned)zz < DD;
        size_t idx = colbase + (size_t)zz * SLICE;
        r0[t] = ok ? g_buf[0ull * VTOT + idx] : 0.f;
        r1[t] = ok ? g_buf[1ull * VTOT + idx] : 0.f;
        r2[t] = ok ? g_buf[2ull * VTOT + idx] : 0.f;
        r3[t] = ok ? g_buf[3ull * VTOT + idx] : 0.f;
        r4[t] = ok ? g_buf[4ull * VTOT + idx] : 0.f;
    }

    float fsum = 0.f;
    #pragma unroll
    for (int oz = 0; oz < 32; ++oz) {
        float mu1 = 0.f, mu2 = 0.f, c11 = 0.f, c22 = 0.f, c12 = 0.f;
        #pragma unroll
        for (int t = 0; t < WS; ++t) {
            mu1 += w[t] * r0[t];
            mu2 += w[t] * r1[t];
            c11 += w[t] * r2[t];
            c22 += w[t] * r3[t];
            c12 += w[t] * r4[t];
        }
        float mu1sq = mu1 * mu1, mu2sq = mu2 * mu2, mu12 = mu1 * mu2;
        float s11 = c11 - mu1sq;
        float s22 = c22 - mu2sq;
        float s12 = c12 - mu12;
        float num = (2.f * mu12 + C1F) * (2.f * s12 + C2F);
        float den = (mu1sq + mu2sq + C1F) * (s11 + s22 + C2F);
        fsum += num / den;

        // shift ring, load next z plane (z + RAD + 1)
        int zz = zc * 32 + oz + RAD + 1;
        bool ok = (unsigned)zz < DD;
        size_t idx = colbase + (size_t)zz * SLICE;
        float n0 = ok ? g_buf[0ull * VTOT + idx] : 0.f;
        float n1 = ok ? g_buf[1ull * VTOT + idx] : 0.f;
        float n2 = ok ? g_buf[2ull * VTOT + idx] : 0.f;
        float n3 = ok ? g_buf[3ull * VTOT + idx] : 0.f;
        float n4 = ok ? g_buf[4ull * VTOT + idx] : 0.f;
        #pragma unroll
        for (int t = 0; t < WS - 1; ++t) {
            r0[t] = r0[t + 1]; r1[t] = r1[t + 1]; r2[t] = r2[t + 1];
            r3[t] = r3[t + 1]; r4[t] = r4[t + 1];
        }
        r0[WS - 1] = n0; r1[WS - 1] = n1; r2[WS - 1] = n2;
        r3[WS - 1] = n3; r4[WS - 1] = n4;
    }

    // Block reduction into the global double accumulator.
    double dsum = (double)fsum;
    #pragma unroll
    for (int off = 16; off > 0; off >>= 1)
        dsum += __shfl_down_sync(0xffffffffu, dsum, off);

    __shared__ double ssum[4];
    int wid = threadIdx.x >> 5, lid = threadIdx.x & 31;
    if (lid == 0) ssum[wid] = dsum;
    __syncthreads();
    if (threadIdx.x == 0) {
        double tot = ssum[0] + ssum[1] + ssum[2] + ssum[3];
        atomicAdd(&g_acc, tot);
    }
}

// ---------------------------------------------------------------------------
// K3: finalize the mean.
// ---------------------------------------------------------------------------
__global__ void finalize_kernel(float* __restrict__ out) {
    out[0] = (float)(g_acc * (1.0 / (double)VTOT));
}

// ---------------------------------------------------------------------------
extern "C" void kernel_launch(void* const* d_in, const int* in_sizes, int n_in,
                              void* d_out, int out_size) {
    (void)in_sizes; (void)n_in; (void)out_size;
    const float* img1   = (const float*)d_in[0];
    const float* img2   = (const float*)d_in[1];
    const float* window = (const float*)d_in[2];

    prep_kernel<<<1, 32>>>(window);

    dim3 g1(HH / TILE, WW / TILE, BATCH * DD);   // (4, 4, 512)
    conv_xy_kernel<<<g1, 256>>>(img1, img2);

    dim3 g2(DD / 32, HH, BATCH);                 // (4, 128, 4)
    conv_z_ssim_kernel<<<g2, 128>>>();

    finalize_kernel<<<1, 1>>>((float*)d_out);
}